// round 6
// baseline (speedup 1.0000x reference)
#include <cuda_runtime.h>

#define CAM_FL  540.0f
#define HALF_W  320.0f
#define HALF_H  240.0f
#define CAM_W   640
#define CAM_H   480
#define PB      512      // particles per block (k_project)
#define TPBP    512      // threads per block, k_project (1 particle/thread)
#define TPBS    256      // threads per block, k_splat

// Global scratch: survivor records. 800000 records x 4 float4 (64B) = 51.2 MB.
// record (16 floats): [0..7]=wx8 (aligned, pre-masked) [8]=z
//                     [9]=packed(bx | (ib+4)<<10 | b<<19)  [10..14]=wy[0..4] [15]=pad
__device__ float4 g_rec[800000 * 4];
__device__ int    g_cnt;

__global__ __launch_bounds__(TPBP) void k_project(
    const float* __restrict__ locs,
    const float* __restrict__ pose,
    const float* __restrict__ rotq,
    int N)
{
    __shared__ float s_rec[PB][16];
    __shared__ int   s_cnt;
    __shared__ int   s_base;

    const int tid = threadIdx.x;
    const int b   = blockIdx.y;

    if (tid == 0) s_cnt = 0;

    // quaternion (normalized, conjugated) -> rotation matrix
    float qx = __ldg(rotq + b * 4 + 0);
    float qy = __ldg(rotq + b * 4 + 1);
    float qz = __ldg(rotq + b * 4 + 2);
    float qw = __ldg(rotq + b * 4 + 3);
    float inv = rsqrtf(qx * qx + qy * qy + qz * qz + qw * qw);
    qx = -qx * inv; qy = -qy * inv; qz = -qz * inv; qw = qw * inv;

    const float qx2 = qx * qx, qy2 = qy * qy, qz2 = qz * qz;
    const float qxqy = qx * qy, qxqz = qx * qz, qxqw = qx * qw;
    const float qyqz = qy * qz, qyqw = qy * qw, qzqw = qz * qw;
    const float r00 = 1.f - 2.f * qy2 - 2.f * qz2;
    const float r10 = 2.f * qxqy - 2.f * qzqw;
    const float r20 = 2.f * qxqz + 2.f * qyqw;
    const float r01 = 2.f * qxqy + 2.f * qzqw;
    const float r11 = 1.f - 2.f * qx2 - 2.f * qz2;
    const float r21 = 2.f * qyqz - 2.f * qxqw;
    const float r02 = 2.f * qxqz - 2.f * qyqw;
    const float r12 = 2.f * qyqz + 2.f * qxqw;
    const float r22 = 1.f - 2.f * qx2 - 2.f * qy2;

    const float cx = __ldg(pose + b * 3 + 0);
    const float cy = __ldg(pose + b * 3 + 1);
    const float cz = __ldg(pose + b * 3 + 2);

    __syncthreads();

    const float C1 = 0.60653066f;   // exp(-0.5)
    const float C2 = 0.13533528f;   // exp(-2)

    const int i = blockIdx.x * PB + tid;

    float X = 0.f, Y = 0.f, Z = 0.f;
    if (i < N) {
        const float* lp = locs + ((long long)b * N + i) * 3;
        X = lp[0]; Y = lp[1]; Z = lp[2];
    }

    const float p0 = X - cx, p1 = Y - cy, p2 = Z - cz;
    const float x = p0 * r00 + p1 * r10 + p2 * r20;
    const float y = p0 * r01 + p1 * r11 + p2 * r21;
    const float z = p0 * r02 + p1 * r12 + p2 * r22;

    bool ok = false;
    float px = 0.f, py = 0.f;
    if (i < N && z > 0.f) {
        const float invz = __frcp_rn(z);
        px = x * invz * CAM_FL + HALF_W;
        py = y * invz * CAM_FL + HALF_H;
        ok = (px >= -2.f && px < 642.f && py >= -2.f && py < 482.f);
    }

    // warp-aggregated compaction
    const unsigned m = __ballot_sync(0xffffffffu, ok);
    int idx = 0;
    if (m) {
        const int lane = tid & 31;
        const int lead = __ffs(m) - 1;
        int wbase = 0;
        if (lane == lead) wbase = atomicAdd(&s_cnt, __popc(m));
        wbase = __shfl_sync(0xffffffffu, wbase, lead);
        idx = wbase + __popc(m & ((1u << lane) - 1u));
    }

    if (ok) {
        const float fx = floorf(px), fy = floorf(py);
        const int jb = (int)fx - 2;
        const int ib = (int)fy - 2;                 // in [-4, 479]
        const int bx = min(max(jb, 0) & ~3, 632);   // aligned 8-slot window start
        const int off = jb - bx;                    // in [-2, 7]

        const float u = fx - px;
        const float v = fy - py;

        float* r = s_rec[idx];
        *(float4*)(r)     = make_float4(0.f, 0.f, 0.f, 0.f);
        *(float4*)(r + 4) = make_float4(0.f, 0.f, 0.f, 0.f);

        const float ax  = __expf(-0.5f * u * u);
        const float ex  = __expf(-u);
        const float exi = __frcp_rn(ex);
        // slots outside [0,7] correspond exactly to out-of-image pixels
        int s;
        s = off + 0; if (s >= 0 && s <= 7) r[s] = ax * exi * exi * C2;
        s = off + 1; if (s >= 0 && s <= 7) r[s] = ax * exi * C1;
        s = off + 2; if (s >= 0 && s <= 7) r[s] = ax;
        s = off + 3; if (s >= 0 && s <= 7) r[s] = ax * ex * C1;
        s = off + 4; if (s >= 0 && s <= 7) r[s] = ax * ex * ex * C2;

        const float ay  = __expf(-0.5f * v * v);
        const float ey  = __expf(-v);
        const float eyi = __frcp_rn(ey);
        r[8]  = z;
        // biased pack: bx in [0,632] (10 bits), ib+4 in [0,483] (9 bits), b<4
        r[9]  = __int_as_float(bx | ((ib + 4) << 10) | (b << 19));
        r[10] = ay * eyi * eyi * C2;
        r[11] = ay * eyi * C1;
        r[12] = ay;
        r[13] = ay * ey * C1;
        r[14] = ay * ey * ey * C2;
        r[15] = 0.f;
    }

    __syncthreads();
    if (tid == 0) s_base = atomicAdd(&g_cnt, s_cnt);
    __syncthreads();

    // coalesced copy-out: cnt*4 float4s, contiguous in smem and gmem
    const int n4 = s_cnt * 4;
    const int gb = s_base * 4;
    const float4* sm4 = (const float4*)s_rec;
    for (int r = tid; r < n4; r += TPBP) {
        g_rec[gb + r] = sm4[r];
    }
}

__global__ __launch_bounds__(TPBS) void k_splat(
    const float* __restrict__ depth,
    float* __restrict__ out)
{
    const int total  = g_cnt * 5;
    const int stride = gridDim.x * blockDim.x;

    for (int t = blockIdx.x * blockDim.x + threadIdx.x; t < total; t += stride) {
        const int s  = t / 5;
        const int ii = t - s * 5;

        const float* r = (const float*)(g_rec + s * 4);
        const int pk = __float_as_int(__ldg(r + 9));
        const int yy = ((pk >> 10) & 0x1ff) - 4 + ii;
        if (yy < 0 || yy >= CAM_H) continue;

        const int bx = pk & 0x3ff;
        const int bb = pk >> 19;

        const float z  = __ldg(r + 8);
        const float wy = __ldg(r + 10 + ii);
        const float4 wa = __ldg((const float4*)r);
        const float4 wb = __ldg((const float4*)r + 1);

        const int o = bb * (CAM_H * CAM_W) + yy * CAM_W + bx;
        float* op = out + o;
        const float4 d0 = *(const float4*)(depth + o);
        const float4 d1 = *(const float4*)(depth + o + 4);

        // predicated scalar REDs: only taps that are nonzero AND pass depth
        // consume LSU lane slots (~3.7 active of 8 on average).
        if (wa.x != 0.f && z <= d0.x) atomicAdd(op + 0, wy * wa.x);
        if (wa.y != 0.f && z <= d0.y) atomicAdd(op + 1, wy * wa.y);
        if (wa.z != 0.f && z <= d0.z) atomicAdd(op + 2, wy * wa.z);
        if (wa.w != 0.f && z <= d0.w) atomicAdd(op + 3, wy * wa.w);
        if (wb.x != 0.f && z <= d1.x) atomicAdd(op + 4, wy * wb.x);
        if (wb.y != 0.f && z <= d1.y) atomicAdd(op + 5, wy * wb.y);
        if (wb.z != 0.f && z <= d1.z) atomicAdd(op + 6, wy * wb.z);
        if (wb.w != 0.f && z <= d1.w) atomicAdd(op + 7, wy * wb.w);
    }
}

extern "C" void kernel_launch(void* const* d_in, const int* in_sizes, int n_in,
                              void* d_out, int out_size) {
    const float* locs  = (const float*)d_in[0];
    const float* pose  = (const float*)d_in[1];
    const float* rotq  = (const float*)d_in[2];
    const float* depth = (const float*)d_in[3];
    float* out = (float*)d_out;

    const int B = in_sizes[1] / 3;           // 4
    const int N = in_sizes[0] / (3 * B);     // 200000

    void* cnt_addr = nullptr;
    cudaGetSymbolAddress(&cnt_addr, g_cnt);
    cudaMemsetAsync(cnt_addr, 0, sizeof(int), 0);
    cudaMemsetAsync(d_out, 0, (size_t)out_size * sizeof(float), 0);

    dim3 grid((N + PB - 1) / PB, B);
    k_project<<<grid, TPBP>>>(locs, pose, rotq, N);
    k_splat<<<1024, TPBS>>>(depth, out);
}

// round 7
// speedup vs baseline: 1.6293x; 1.6293x over previous
#include <cuda_runtime.h>

#define CAM_FL  540.0f
#define HALF_W  320.0f
#define HALF_H  240.0f
#define CAM_W   640
#define CAM_H   480
#define HW      (CAM_H * CAM_W)
#define PB      512      // particles per block
#define TPB     256      // threads per block
#define CAP     128      // smem survivor capacity (mean ~23/block; overflow -> slow path)

__global__ __launch_bounds__(TPB) void proj_kernel(
    const float* __restrict__ locs,
    const float* __restrict__ pose,
    const float* __restrict__ rotq,
    const float* __restrict__ depth,
    float* __restrict__ out,
    int N)
{
    // record (16 floats): [0..7]=wx8 (aligned 8-slot x weights, pre-masked)
    // [8]=z  [9]=packed(bx | (ib+4)<<10 | b<<19)  [10..14]=wy[0..4]  [15]=pad
    __shared__ float s_rec[CAP][16];
    __shared__ int   s_cnt;

    const int tid = threadIdx.x;
    const int b   = blockIdx.y;

    if (tid == 0) s_cnt = 0;

    // --- quaternion (normalized, conjugated) -> rotation matrix ---
    float qx = __ldg(rotq + b * 4 + 0);
    float qy = __ldg(rotq + b * 4 + 1);
    float qz = __ldg(rotq + b * 4 + 2);
    float qw = __ldg(rotq + b * 4 + 3);
    float inv = rsqrtf(qx * qx + qy * qy + qz * qz + qw * qw);
    qx = -qx * inv; qy = -qy * inv; qz = -qz * inv; qw = qw * inv;

    const float qx2 = qx * qx, qy2 = qy * qy, qz2 = qz * qz;
    const float qxqy = qx * qy, qxqz = qx * qz, qxqw = qx * qw;
    const float qyqz = qy * qz, qyqw = qy * qw, qzqw = qz * qw;
    const float r00 = 1.f - 2.f * qy2 - 2.f * qz2;
    const float r10 = 2.f * qxqy - 2.f * qzqw;
    const float r20 = 2.f * qxqz + 2.f * qyqw;
    const float r01 = 2.f * qxqy + 2.f * qzqw;
    const float r11 = 1.f - 2.f * qx2 - 2.f * qz2;
    const float r21 = 2.f * qyqz - 2.f * qxqw;
    const float r02 = 2.f * qxqz - 2.f * qyqw;
    const float r12 = 2.f * qyqz + 2.f * qxqw;
    const float r22 = 1.f - 2.f * qx2 - 2.f * qy2;

    const float cx = __ldg(pose + b * 3 + 0);
    const float cy = __ldg(pose + b * 3 + 1);
    const float cz = __ldg(pose + b * 3 + 2);

    const float* dimg = depth + b * HW;
    float*       oimg = out   + b * HW;

    __syncthreads();   // s_cnt init visible

    // ---------------- Phase 1: project 2 paired particles/thread, compact ----------------
    const float C1 = 0.60653066f;   // exp(-0.5)
    const float C2 = 0.13533528f;   // exp(-2)

    const int  gpart = blockIdx.x * PB;
    const float* lpB = locs + ((long long)b * N + gpart) * 3;
    const int  i0 = 2 * tid;

    float X[2], Y[2], Z[2];
    const bool has1 = (gpart + i0 + 1) < N;
    const bool has0 = (gpart + i0) < N;
    if (has1) {
        const float2 A  = *(const float2*)(lpB + i0 * 3);
        const float2 Bv = *(const float2*)(lpB + i0 * 3 + 2);
        const float2 Cv = *(const float2*)(lpB + i0 * 3 + 4);
        X[0] = A.x;  Y[0] = A.y;  Z[0] = Bv.x;
        X[1] = Bv.y; Y[1] = Cv.x; Z[1] = Cv.y;
    } else if (has0) {
        X[0] = lpB[i0 * 3]; Y[0] = lpB[i0 * 3 + 1]; Z[0] = lpB[i0 * 3 + 2];
        X[1] = 0.f; Y[1] = 0.f; Z[1] = 0.f;
    } else {
        X[0] = X[1] = Y[0] = Y[1] = Z[0] = Z[1] = 0.f;
    }

#pragma unroll
    for (int j = 0; j < 2; j++) {
        const float p0 = X[j] - cx, p1 = Y[j] - cy, p2 = Z[j] - cz;
        const float x = p0 * r00 + p1 * r10 + p2 * r20;
        const float y = p0 * r01 + p1 * r11 + p2 * r21;
        const float z = p0 * r02 + p1 * r12 + p2 * r22;

        bool ok = false;
        float px = 0.f, py = 0.f;
        const bool have = (j == 0) ? has0 : has1;
        if (have && z > 0.f) {
            const float invz = __frcp_rn(z);
            px = x * invz * CAM_FL + HALF_W;
            py = y * invz * CAM_FL + HALF_H;
            ok = (px >= -2.f && px < 642.f && py >= -2.f && py < 482.f);
        }

        const unsigned m = __ballot_sync(0xffffffffu, ok);
        int idx = 0;
        if (m) {
            const int lane = tid & 31;
            const int lead = __ffs(m) - 1;
            int wbase = 0;
            if (lane == lead) wbase = atomicAdd(&s_cnt, __popc(m));
            wbase = __shfl_sync(0xffffffffu, wbase, lead);
            idx = wbase + __popc(m & ((1u << lane) - 1u));
        }

        if (ok) {
            const float fx = floorf(px), fy = floorf(py);
            const int jb = (int)fx - 2;
            const int ib = (int)fy - 2;                 // in [-4, 479]
            const float u = fx - px;
            const float v = fy - py;

            const float ax  = __expf(-0.5f * u * u);
            const float ex  = __expf(-u);
            const float exi = __frcp_rn(ex);
            const float wx0 = ax * exi * exi * C2;
            const float wx1 = ax * exi * C1;
            const float wx2 = ax;
            const float wx3 = ax * ex * C1;
            const float wx4 = ax * ex * ex * C2;

            const float ay  = __expf(-0.5f * v * v);
            const float ey  = __expf(-v);
            const float eyi = __frcp_rn(ey);
            const float wy0 = ay * eyi * eyi * C2;
            const float wy1 = ay * eyi * C1;
            const float wy2 = ay;
            const float wy3 = ay * ey * C1;
            const float wy4 = ay * ey * ey * C2;

            if (idx < CAP) {
                const int bx = min(max(jb, 0) & ~3, 632);   // aligned 8-slot window
                const int off = jb - bx;                    // in [-2, 7]

                float* r = s_rec[idx];
                *(float4*)(r)     = make_float4(0.f, 0.f, 0.f, 0.f);
                *(float4*)(r + 4) = make_float4(0.f, 0.f, 0.f, 0.f);
                int s;
                s = off + 0; if (s >= 0 && s <= 7) r[s] = wx0;
                s = off + 1; if (s >= 0 && s <= 7) r[s] = wx1;
                s = off + 2; if (s >= 0 && s <= 7) r[s] = wx2;
                s = off + 3; if (s >= 0 && s <= 7) r[s] = wx3;
                s = off + 4; if (s >= 0 && s <= 7) r[s] = wx4;
                r[8]  = z;
                r[9]  = __int_as_float(bx | ((ib + 4) << 10) | (b << 19));
                r[10] = wy0; r[11] = wy1; r[12] = wy2; r[13] = wy3; r[14] = wy4;
            } else {
                // overflow slow path (statistically unreachable): direct splat
                const float wxv[5] = {wx0, wx1, wx2, wx3, wx4};
                const float wyv[5] = {wy0, wy1, wy2, wy3, wy4};
                for (int ii = 0; ii < 5; ii++) {
                    const int yy = ib + ii;
                    if (yy < 0 || yy >= CAM_H) continue;
                    for (int jj = 0; jj < 5; jj++) {
                        const int xx = jb + jj;
                        if (xx < 0 || xx >= CAM_W) continue;
                        const float d = __ldg(dimg + yy * CAM_W + xx);
                        if (z <= d) atomicAdd(oimg + yy * CAM_W + xx, wyv[ii] * wxv[jj]);
                    }
                }
            }
        }
    }

    __syncthreads();

    // ---------------- Phase 2: warp-coalesced splat ----------------
    // 8 consecutive lanes own the 8 aligned slots of one survivor; a warp
    // processes 4 survivors. Depth loads and reds hit 4 contiguous 32B
    // segments per warp-op (coalesced), 5 rows loaded up-front (MLP=5).
    const int cnt  = min(s_cnt, CAP);
    const int wid  = tid >> 5;
    const int lane = tid & 31;
    const int sub  = lane >> 3;     // 0..3: survivor within warp-task
    const int slot = lane & 7;      // 0..7: x-slot

    for (int s0 = wid * 4; s0 < cnt; s0 += (TPB / 32) * 4) {
        const int s = s0 + sub;
        if (s >= cnt) continue;

        const float* r = s_rec[s];
        const float wx = r[slot];
        const float z  = r[8];
        const int   pk = __float_as_int(r[9]);
        const int   bx = pk & 0x3ff;
        const int   ib = ((pk >> 10) & 0x1ff) - 4;

        const int base = ib * CAM_W + bx + slot;

        float dd[5];
        int   oo[5];
        bool  rk[5];
#pragma unroll
        for (int row = 0; row < 5; row++) {
            const int yy = ib + row;
            rk[row] = (yy >= 0) && (yy < CAM_H) && (wx != 0.f);
            oo[row] = base + row * CAM_W;
            dd[row] = rk[row] ? __ldg(dimg + oo[row]) : -1.f;
        }
#pragma unroll
        for (int row = 0; row < 5; row++) {
            if (rk[row] && z <= dd[row]) {
                atomicAdd(oimg + oo[row], r[10 + row] * wx);
            }
        }
    }
}

extern "C" void kernel_launch(void* const* d_in, const int* in_sizes, int n_in,
                              void* d_out, int out_size) {
    const float* locs  = (const float*)d_in[0];
    const float* pose  = (const float*)d_in[1];
    const float* rotq  = (const float*)d_in[2];
    const float* depth = (const float*)d_in[3];
    float* out = (float*)d_out;

    const int B = in_sizes[1] / 3;           // 4
    const int N = in_sizes[0] / (3 * B);     // 200000

    cudaMemsetAsync(d_out, 0, (size_t)out_size * sizeof(float), 0);

    dim3 grid((N + PB - 1) / PB, B);
    proj_kernel<<<grid, TPB>>>(locs, pose, rotq, depth, out, N);
}